// round 7
// baseline (speedup 1.0000x reference)
#include <cuda_runtime.h>
#include <math_constants.h>

#define B_   32
#define N_   1024
#define F_   64
#define K_   16
#define P_   128
#define H_   256     // 2*P
#define NPB  4       // points per block
#define M_   (NPB * K_)   // 64 GEMM rows per block
#define AST  68      // padded SMEM row stride (floats), 16B-aligned
#define HST  68

typedef unsigned long long ull;

__device__ int g_idx[B_ * N_ * K_];

// ---------------------------------------------------------------------------
// Kernel 1: pairwise distances + top-(K+1) selection (drop self).
// ---------------------------------------------------------------------------
__global__ __launch_bounds__(256) void knn_kernel(const float* __restrict__ points)
{
    __shared__ float4 pts[N_];
    int b = blockIdx.x >> 2;
    int rowbase = (blockIdx.x & 3) << 8;
    const float* P = points + (size_t)b * N_ * 3;
    for (int i = threadIdx.x; i < N_; i += 256) {
        float x = P[i * 3 + 0], y = P[i * 3 + 1], z = P[i * 3 + 2];
        pts[i] = make_float4(x, y, z, x * x + y * y + z * z);
    }
    __syncthreads();

    int n = rowbase + threadIdx.x;
    float4 pn = pts[n];

    float dist[K_ + 1];
    int   nbr[K_ + 1];
#pragma unroll
    for (int j = 0; j <= K_; j++) { dist[j] = CUDART_INF_F; nbr[j] = 0; }
    float worst = CUDART_INF_F;

    for (int m = 0; m < N_; m++) {
        float4 pm = pts[m];
        float dot = pn.x * pm.x + pn.y * pm.y + pn.z * pm.z;
        float d = pn.w - 2.0f * dot + pm.w + 1e-5f;
        if (d < worst) {
            int j = K_;
            for (; j > 0; j--) {
                if (dist[j - 1] > d) { dist[j] = dist[j - 1]; nbr[j] = nbr[j - 1]; }
                else break;
            }
            dist[j] = d; nbr[j] = m;
            worst = dist[K_];
        }
    }

    int* o = g_idx + ((size_t)b * N_ + n) * K_;
#pragma unroll
    for (int k = 0; k < K_; k++) o[k] = nbr[k + 1];
}

// ---------------------------------------------------------------------------
// f32x2 helpers
// ---------------------------------------------------------------------------
__device__ __forceinline__ void unpack2(ull v, float& lo, float& hi)
{
    asm("mov.b64 {%0, %1}, %2;" : "=f"(lo), "=f"(hi) : "l"(v));
}
__device__ __forceinline__ ull dup2(float x)
{
    ull r;
    asm("mov.b64 %0, {%1, %1};" : "=l"(r) : "f"(x));
    return r;
}
__device__ __forceinline__ ull ffma2(ull a, ull b, ull c)
{
    ull d;
    asm("fma.rn.f32x2 %0, %1, %2, %3;" : "=l"(d) : "l"(a), "l"(b), "l"(c));
    return d;
}
__device__ __forceinline__ float gelu_exact(float x)
{
    return 0.5f * x * (1.0f + erff(x * 0.70710678118654752440f));
}

// ---------------------------------------------------------------------------
// Kernel 2: fused edge MLP + mean over K.
// Block = NPB=4 points = 64 edge rows.
//   A[64x128] @ W1[128x256] -> gelu -> H[64x256] @ W2[256x128] -> gelu -> mean16
// f32x2 lanes ride the N dimension: weight pairs come straight from memory
// (ulonglong2 loads, zero packs); only the 4 A scalars get a dup MOV each.
// Thread grid 16(tm) x 16(tn): phase1 tile M'=4 x N'=16, phase2 M'=4 x N'=8.
// ---------------------------------------------------------------------------
__global__ __launch_bounds__(256, 2) void mlp_kernel(
    const float* __restrict__ features,
    const float* __restrict__ W1, const float* __restrict__ b1,
    const float* __restrict__ W2, const float* __restrict__ b2,
    float* __restrict__ out)
{
    extern __shared__ float smem[];
    float* As   = smem;                      // [128][AST]  rows = feature idx, cols = m
    float* Hsm  = As  + 128 * AST;           // [256][HST]  rows = hidden idx,  cols = m
    float* cenS = Hsm + 256 * HST;           // [4][64]
    int*   nbS  = (int*)(cenS + NPB * F_);   // [64]

    int blk = blockIdx.x;
    int b  = blk >> 8;
    int n0 = (blk & 255) * NPB;
    const float* Fb = features + (size_t)b * N_ * F_;
    int t = threadIdx.x;

    {
        int nl = t >> 6, f = t & 63;
        cenS[t] = Fb[(size_t)(n0 + nl) * F_ + f];
    }
    if (t < M_) nbS[t] = g_idx[((size_t)b * N_ + n0 + (t >> 4)) * K_ + (t & 15)];
    __syncthreads();

    // gather: As[f][m] = nbr - ctr, As[64+f][m] = ctr   (m = nl*16 + k)
#pragma unroll
    for (int i = 0; i < 16; i++) {
        int e  = t + i * 256;
        int nl = e >> 10;
        int k  = (e >> 6) & 15;
        int f  = e & 63;
        int m  = nl * K_ + k;
        float c = cenS[nl * F_ + f];
        float v = Fb[(size_t)nbS[m] * F_ + f];
        As[f * AST + m]        = v - c;
        As[(F_ + f) * AST + m] = c;
    }
    __syncthreads();

    int tm = t & 15;       // m-chunk: rows tm*4 .. tm*4+3
    int tn = t >> 4;       // 0..15

    // ---------------- phase 1: A[64x128] @ W1[128x256] ----------------
    {
        int nb1 = tn * 16;                       // 16 N columns = 8 pairs
        ull acc[4][8];                           // [m][n-pair]
        {
            const ull* bp = (const ull*)(b1 + nb1);
#pragma unroll
            for (int j = 0; j < 8; j++) {
                ull bv = bp[j];
#pragma unroll
                for (int m = 0; m < 4; m++) acc[m][j] = bv;
            }
        }
        const float* w1p = W1 + nb1;
        const float* ap  = As + tm * 4;
#pragma unroll 2
        for (int k = 0; k < 2 * F_; k++) {
            const ulonglong2* wp = (const ulonglong2*)(w1p + k * H_);
            ulonglong2 wv0 = wp[0], wv1 = wp[1], wv2 = wp[2], wv3 = wp[3];
            ull w[8] = {wv0.x, wv0.y, wv1.x, wv1.y, wv2.x, wv2.y, wv3.x, wv3.y};
            float4 av = *(const float4*)(ap + k * AST);
            ull a0 = dup2(av.x), a1 = dup2(av.y), a2 = dup2(av.z), a3 = dup2(av.w);
#pragma unroll
            for (int j = 0; j < 8; j++) {
                acc[0][j] = ffma2(a0, w[j], acc[0][j]);
                acc[1][j] = ffma2(a1, w[j], acc[1][j]);
                acc[2][j] = ffma2(a2, w[j], acc[2][j]);
                acc[3][j] = ffma2(a3, w[j], acc[3][j]);
            }
        }
        // epilogue: gelu -> Hsm[j][m]  (scalar stores: pair spans two j-rows)
#pragma unroll
        for (int j = 0; j < 8; j++) {
#pragma unroll
            for (int m = 0; m < 4; m++) {
                float g0, g1; unpack2(acc[m][j], g0, g1);
                Hsm[(nb1 + 2 * j)     * HST + tm * 4 + m] = gelu_exact(g0);
                Hsm[(nb1 + 2 * j + 1) * HST + tm * 4 + m] = gelu_exact(g1);
            }
        }
    }
    __syncthreads();

    // ---------------- phase 2: H[64x256] @ W2[256x128] ----------------
    {
        int n2 = tn * 8;                         // 8 N columns = 4 pairs
        ull acc[4][4];
        {
            const ull* bp = (const ull*)(b2 + n2);
#pragma unroll
            for (int j = 0; j < 4; j++) {
                ull bv = bp[j];
#pragma unroll
                for (int m = 0; m < 4; m++) acc[m][j] = bv;
            }
        }
        const float* w2p = W2 + n2;
        const float* hp  = Hsm + tm * 4;
#pragma unroll 4
        for (int k = 0; k < H_; k++) {
            const ulonglong2* wp = (const ulonglong2*)(w2p + k * P_);
            ulonglong2 wv0 = wp[0], wv1 = wp[1];
            ull w[4] = {wv0.x, wv0.y, wv1.x, wv1.y};
            float4 hv = *(const float4*)(hp + k * HST);
            ull h0 = dup2(hv.x), h1 = dup2(hv.y), h2 = dup2(hv.z), h3 = dup2(hv.w);
#pragma unroll
            for (int j = 0; j < 4; j++) {
                acc[0][j] = ffma2(h0, w[j], acc[0][j]);
                acc[1][j] = ffma2(h1, w[j], acc[1][j]);
                acc[2][j] = ffma2(h2, w[j], acc[2][j]);
                acc[3][j] = ffma2(h3, w[j], acc[3][j]);
            }
        }
        // epilogue: gelu + sum this thread's 4 k-rows, shuffle-reduce 4-lane
        // tm group -> mean over 16, write 8 cols for point n0 + tm/4.
        float s[8];
#pragma unroll
        for (int j = 0; j < 4; j++) { s[2 * j] = 0.f; s[2 * j + 1] = 0.f; }
#pragma unroll
        for (int m = 0; m < 4; m++) {
#pragma unroll
            for (int j = 0; j < 4; j++) {
                float g0, g1; unpack2(acc[m][j], g0, g1);
                s[2 * j]     += gelu_exact(g0);
                s[2 * j + 1] += gelu_exact(g1);
            }
        }
#pragma unroll
        for (int j = 0; j < 8; j++) {
            s[j] += __shfl_down_sync(0xffffffffu, s[j], 1);
            s[j] += __shfl_down_sync(0xffffffffu, s[j], 2);
        }
        if ((tm & 3) == 0) {
            int nrow = n0 + (tm >> 2);
            float4 o0 = make_float4(s[0] * (1.0f / 16.0f), s[1] * (1.0f / 16.0f),
                                    s[2] * (1.0f / 16.0f), s[3] * (1.0f / 16.0f));
            float4 o1 = make_float4(s[4] * (1.0f / 16.0f), s[5] * (1.0f / 16.0f),
                                    s[6] * (1.0f / 16.0f), s[7] * (1.0f / 16.0f));
            float* op = out + ((size_t)b * N_ + nrow) * P_ + n2;
            *(float4*)(op)     = o0;
            *(float4*)(op + 4) = o1;
        }
    }
}

// ---------------------------------------------------------------------------
extern "C" void kernel_launch(void* const* d_in, const int* in_sizes, int n_in,
                              void* d_out, int out_size)
{
    const float* points   = (const float*)d_in[0];
    const float* features = (const float*)d_in[1];
    const float* W1       = (const float*)d_in[2];
    const float* b1       = (const float*)d_in[3];
    const float* W2       = (const float*)d_in[4];
    const float* b2       = (const float*)d_in[5];
    float* out = (float*)d_out;

    const int smem_bytes = (128 * AST + 256 * HST + NPB * F_) * 4 + 64 * 4;
    cudaFuncSetAttribute(mlp_kernel, cudaFuncAttributeMaxDynamicSharedMemorySize,
                         smem_bytes);

    knn_kernel<<<B_ * 4, 256>>>(points);
    mlp_kernel<<<(B_ * N_) / NPB, 256, smem_bytes>>>(features, W1, b1, W2, b2, out);
}

// round 10
// speedup vs baseline: 1.4294x; 1.4294x over previous
#include <cuda_runtime.h>
#include <cuda_bf16.h>
#include <math_constants.h>
#include <cstdint>

#define B_   32
#define N_   1024
#define F_   64
#define K_   16
#define P_   128
#define H_   256
#define NPB  8              // points per block
#define M_   128            // GEMM rows per block

typedef unsigned long long ull;

// ---------------------------------------------------------------------------
// device scratch (static — no allocation)
// g_w1: half h (output cols h*128..): image [128 n_local][128 k] bf16
// g_w2: chunk c (k cols c*128..):     image [128 p][128 j_local] bf16
// ---------------------------------------------------------------------------
__device__ int g_idx[B_ * N_ * K_];
__device__ __align__(16) unsigned char g_w1hi[2][32768];
__device__ __align__(16) unsigned char g_w1lo[2][32768];
__device__ __align__(16) unsigned char g_w2hi[2][32768];
__device__ __align__(16) unsigned char g_w2lo[2][32768];

// ---------------------------------------------------------------------------
// SMEM layout (dynamic, bytes)
// ---------------------------------------------------------------------------
#define SM_AHI  0
#define SM_ALO  32768
#define SM_HHI  65536
#define SM_HLO  98304
#define SM_WHI  131072
#define SM_WLO  163840
#define SM_MISC 196608
#define SM_NBS  (SM_MISC + 0)        // 128 ints
#define SM_CENS (SM_MISC + 512)      // 512 floats
#define SM_B1S  (SM_MISC + 2560)     // 256 floats
#define SM_B2S  (SM_MISC + 3584)     // 128 floats
#define SMEM_TOTAL (SM_MISC + 4096)

// ---------------------------------------------------------------------------
// image addressing: row-major [R rows][128 bf16], 256B/row,
// 16B chunks XOR-swizzled by row&7 -> conflict-free ldmatrix
// ---------------------------------------------------------------------------
__device__ __forceinline__ uint32_t img_off(int r, int c)
{
    return (uint32_t)(r * 256) + (uint32_t)((((c >> 3) ^ (r & 7)) << 4) + (c & 7) * 2);
}
__device__ __forceinline__ uint32_t img_addr(uint32_t base, int row, int chunk)
{
    return base + (uint32_t)(row * 256) + (uint32_t)(((chunk ^ (row & 7)) << 4));
}

__device__ __forceinline__ uint32_t smem_to_u32(const void* p)
{
    uint32_t a;
    asm("{ .reg .u64 t; cvta.to.shared.u64 t, %1; cvt.u32.u64 %0, t; }"
        : "=r"(a) : "l"(p));
    return a;
}

// ---------------------------------------------------------------------------
// ldmatrix / mma wrappers (baseline PTX, no sm_103a-gated features)
// ---------------------------------------------------------------------------
__device__ __forceinline__ void ldm_x4(uint32_t* r, uint32_t addr)
{
    asm volatile("ldmatrix.sync.aligned.m8n8.x4.shared.b16 {%0,%1,%2,%3}, [%4];"
                 : "=r"(r[0]), "=r"(r[1]), "=r"(r[2]), "=r"(r[3]) : "r"(addr));
}
__device__ __forceinline__ void ldm_x2(uint32_t* r, uint32_t addr)
{
    asm volatile("ldmatrix.sync.aligned.m8n8.x2.shared.b16 {%0,%1}, [%2];"
                 : "=r"(r[0]), "=r"(r[1]) : "r"(addr));
}
__device__ __forceinline__ void mma_bf16(float* d, const uint32_t* a, const uint32_t* b)
{
    asm volatile(
        "mma.sync.aligned.m16n8k16.row.col.f32.bf16.bf16.f32 "
        "{%0,%1,%2,%3}, {%4,%5,%6,%7}, {%8,%9}, {%0,%1,%2,%3};"
        : "+f"(d[0]), "+f"(d[1]), "+f"(d[2]), "+f"(d[3])
        : "r"(a[0]), "r"(a[1]), "r"(a[2]), "r"(a[3]), "r"(b[0]), "r"(b[1]));
}

__device__ __forceinline__ uint32_t pk2(__nv_bfloat16 a, __nv_bfloat16 b)
{
    uint16_t ua = *(uint16_t*)&a, ub = *(uint16_t*)&b;
    return (uint32_t)ua | ((uint32_t)ub << 16);
}
__device__ __forceinline__ void split4(float v0, float v1, float v2, float v3,
                                       ull& hi, ull& lo)
{
    __nv_bfloat16 h0 = __float2bfloat16(v0), h1 = __float2bfloat16(v1);
    __nv_bfloat16 h2 = __float2bfloat16(v2), h3 = __float2bfloat16(v3);
    __nv_bfloat16 l0 = __float2bfloat16(v0 - __bfloat162float(h0));
    __nv_bfloat16 l1 = __float2bfloat16(v1 - __bfloat162float(h1));
    __nv_bfloat16 l2 = __float2bfloat16(v2 - __bfloat162float(h2));
    __nv_bfloat16 l3 = __float2bfloat16(v3 - __bfloat162float(h3));
    hi = (ull)pk2(h0, h1) | ((ull)pk2(h2, h3) << 32);
    lo = (ull)pk2(l0, l1) | ((ull)pk2(l2, l3) << 32);
}
__device__ __forceinline__ void split2(float v0, float v1, uint32_t& hi, uint32_t& lo)
{
    __nv_bfloat16 h0 = __float2bfloat16(v0), h1 = __float2bfloat16(v1);
    __nv_bfloat16 l0 = __float2bfloat16(v0 - __bfloat162float(h0));
    __nv_bfloat16 l1 = __float2bfloat16(v1 - __bfloat162float(h1));
    hi = pk2(h0, h1); lo = pk2(l0, l1);
}
__device__ __forceinline__ float gelu_exact(float x)
{
    return 0.5f * x * (1.0f + erff(x * 0.70710678118654752440f));
}

// ---------------------------------------------------------------------------
// Kernel 0: weight prep — transpose + bf16 split into swizzled images
// ---------------------------------------------------------------------------
__global__ __launch_bounds__(256) void prep_kernel(const float* __restrict__ W1,
                                                   const float* __restrict__ W2)
{
    int i = blockIdx.x * 256 + threadIdx.x;
    if (i < 32768) {                       // W1^T: n 0..255, k 0..127
        int n = i >> 7, k = i & 127;
        float v = W1[k * H_ + n];
        __nv_bfloat16 h = __float2bfloat16(v);
        __nv_bfloat16 l = __float2bfloat16(v - __bfloat162float(h));
        int hh = n >> 7, nl = n & 127;
        uint32_t off = img_off(nl, k);
        *(__nv_bfloat16*)(g_w1hi[hh] + off) = h;
        *(__nv_bfloat16*)(g_w1lo[hh] + off) = l;
    } else {                               // W2^T: p 0..127, j 0..255
        int j2 = i - 32768;
        int p = j2 >> 8, j = j2 & 255;
        float v = W2[j * P_ + p];
        __nv_bfloat16 h = __float2bfloat16(v);
        __nv_bfloat16 l = __float2bfloat16(v - __bfloat162float(h));
        int c = j >> 7, jl = j & 127;
        uint32_t off = img_off(p, jl);
        *(__nv_bfloat16*)(g_w2hi[c] + off) = h;
        *(__nv_bfloat16*)(g_w2lo[c] + off) = l;
    }
}

// ---------------------------------------------------------------------------
// Kernel 1: KNN (proven correct, unchanged)
// ---------------------------------------------------------------------------
__global__ __launch_bounds__(256) void knn_kernel(const float* __restrict__ points)
{
    __shared__ float4 pts[N_];
    int b = blockIdx.x >> 2;
    int rowbase = (blockIdx.x & 3) << 8;
    const float* P = points + (size_t)b * N_ * 3;
    for (int i = threadIdx.x; i < N_; i += 256) {
        float x = P[i * 3 + 0], y = P[i * 3 + 1], z = P[i * 3 + 2];
        pts[i] = make_float4(x, y, z, x * x + y * y + z * z);
    }
    __syncthreads();

    int n = rowbase + threadIdx.x;
    float4 pn = pts[n];

    float dist[K_ + 1];
    int   nbr[K_ + 1];
#pragma unroll
    for (int j = 0; j <= K_; j++) { dist[j] = CUDART_INF_F; nbr[j] = 0; }
    float worst = CUDART_INF_F;

    for (int m = 0; m < N_; m++) {
        float4 pm = pts[m];
        float dot = pn.x * pm.x + pn.y * pm.y + pn.z * pm.z;
        float d = pn.w - 2.0f * dot + pm.w + 1e-5f;
        if (d < worst) {
            int j = K_;
            for (; j > 0; j--) {
                if (dist[j - 1] > d) { dist[j] = dist[j - 1]; nbr[j] = nbr[j - 1]; }
                else break;
            }
            dist[j] = d; nbr[j] = m;
            worst = dist[K_];
        }
    }

    int* o = g_idx + ((size_t)b * N_ + n) * K_;
#pragma unroll
    for (int k = 0; k < K_; k++) o[k] = nbr[k + 1];
}

// ---------------------------------------------------------------------------
// Kernel 2: fused edge-MLP via split-bf16 mma.sync (3 products, fp32 acc).
// Block = 8 points = 128 edge rows, 8 warps (4 M-groups x 2 N-groups).
// For h in {0,1}:
//   phase1 half: D1[:,h*128..] = A[128x128] @ W1half  -> bias+gelu -> H chunk
//   phase2 part: D2 += H chunk @ W2chunk(h)           (acc in registers)
// Final: bias+gelu+mean16 -> out.
// ---------------------------------------------------------------------------
__global__ __launch_bounds__(256, 1) void mlp_kernel(
    const float* __restrict__ features,
    const float* __restrict__ b1, const float* __restrict__ b2,
    float* __restrict__ out)
{
    extern __shared__ __align__(1024) char smem[];
    uint32_t sb = smem_to_u32(smem);
    int t = threadIdx.x, wid = t >> 5, lane = t & 31;

    int blk = blockIdx.x;
    int b     = blk >> 7;
    int nbase = (blk & 127) * NPB;
    const float* Fb = features + (size_t)b * N_ * F_;

    int*   nbS  = (int*)(smem + SM_NBS);
    float* cenS = (float*)(smem + SM_CENS);
    float* b1s  = (float*)(smem + SM_B1S);
    float* b2s  = (float*)(smem + SM_B2S);

    for (int i = t; i < NPB * F_; i += 256)
        cenS[i] = Fb[(size_t)(nbase + (i >> 6)) * F_ + (i & 63)];
    if (t < M_) nbS[t] = g_idx[((size_t)b * N_ + nbase + (t >> 4)) * K_ + (t & 15)];
    b1s[t] = b1[t];
    if (t < P_) b2s[t] = b2[t];
    __syncthreads();

    // ---- build A image (hi/lo bf16, swizzled) ----
    for (int i = t; i < 4096; i += 256) {
        int m  = i >> 5;
        int fg = (i & 31) << 2;
        float v0, v1, v2, v3;
        if (fg < 64) {
            float4 nv = *(const float4*)(Fb + (size_t)nbS[m] * F_ + fg);
            float4 cv = *(const float4*)(cenS + (m >> 4) * F_ + fg);
            v0 = nv.x - cv.x; v1 = nv.y - cv.y; v2 = nv.z - cv.z; v3 = nv.w - cv.w;
        } else {
            float4 cv = *(const float4*)(cenS + (m >> 4) * F_ + (fg - 64));
            v0 = cv.x; v1 = cv.y; v2 = cv.z; v3 = cv.w;
        }
        ull hi, lo; split4(v0, v1, v2, v3, hi, lo);
        uint32_t off = img_off(m, fg);
        *(ull*)(smem + SM_AHI + off) = hi;
        *(ull*)(smem + SM_ALO + off) = lo;
    }

    int wm = wid & 3, wg = wid >> 2;
    int m0 = wm * 32;
    int n0 = wg * 64;

    float e[2][8][4];
#pragma unroll
    for (int mt = 0; mt < 2; mt++)
#pragma unroll
        for (int nt = 0; nt < 8; nt++)
#pragma unroll
            for (int r = 0; r < 4; r++) e[mt][nt][r] = 0.0f;

#pragma unroll 1
    for (int h = 0; h < 2; h++) {
        // ---- load W1 half images (W region) ----
        __syncthreads();
        {
            const int4* s1 = (const int4*)g_w1hi[h];
            const int4* s2 = (const int4*)g_w1lo[h];
            int4* d1 = (int4*)(smem + SM_WHI);
            int4* d2 = (int4*)(smem + SM_WLO);
            for (int i = t; i < 2048; i += 256) { d1[i] = s1[i]; d2[i] = s2[i]; }
        }
        __syncthreads();

        // ---- phase 1: A[128x128] @ W1half -> d ----
        float d[2][8][4];
#pragma unroll
        for (int mt = 0; mt < 2; mt++)
#pragma unroll
            for (int nt = 0; nt < 8; nt++)
#pragma unroll
                for (int r = 0; r < 4; r++) d[mt][nt][r] = 0.0f;

#pragma unroll 1
        for (int ks = 0; ks < 8; ks++) {
            uint32_t ahi[2][4], alo[2][4];
#pragma unroll
            for (int mt = 0; mt < 2; mt++) {
                int row = m0 + mt * 16 + (lane & 15);
                int ch  = ks * 2 + (lane >> 4);
                ldm_x4(ahi[mt], img_addr(sb + SM_AHI, row, ch));
                ldm_x4(alo[mt], img_addr(sb + SM_ALO, row, ch));
            }
            int brow_lo = lane & 7;
            int bch     = ks * 2 + ((lane >> 3) & 1);
#pragma unroll
            for (int nt = 0; nt < 8; nt++) {
                uint32_t bhi[2], blo[2];
                int row = n0 + nt * 8 + brow_lo;
                ldm_x2(bhi, img_addr(sb + SM_WHI, row, bch));
                ldm_x2(blo, img_addr(sb + SM_WLO, row, bch));
#pragma unroll
                for (int mt = 0; mt < 2; mt++) {
                    mma_bf16(d[mt][nt], ahi[mt], bhi);
                    mma_bf16(d[mt][nt], ahi[mt], blo);
                    mma_bf16(d[mt][nt], alo[mt], bhi);
                }
            }
        }

        // ---- epilogue: bias + gelu -> H images ----
#pragma unroll
        for (int mt = 0; mt < 2; mt++) {
            int row0 = m0 + mt * 16 + (lane >> 2);
#pragma unroll
            for (int nt = 0; nt < 8; nt++) {
                int colb = n0 + nt * 8 + (lane & 3) * 2;
                float bv0 = b1s[h * 128 + colb], bv1 = b1s[h * 128 + colb + 1];
                float v0 = gelu_exact(d[mt][nt][0] + bv0);
                float v1 = gelu_exact(d[mt][nt][1] + bv1);
                float v2 = gelu_exact(d[mt][nt][2] + bv0);
                float v3 = gelu_exact(d[mt][nt][3] + bv1);
                uint32_t hi, lo;
                split2(v0, v1, hi, lo);
                uint32_t off = img_off(row0, colb);
                *(uint32_t*)(smem + SM_HHI + off) = hi;
                *(uint32_t*)(smem + SM_HLO + off) = lo;
                split2(v2, v3, hi, lo);
                off = img_off(row0 + 8, colb);
                *(uint32_t*)(smem + SM_HHI + off) = hi;
                *(uint32_t*)(smem + SM_HLO + off) = lo;
            }
        }
        __syncthreads();

        // ---- load W2 chunk images (overwrite W region) ----
        {
            const int4* s1 = (const int4*)g_w2hi[h];
            const int4* s2 = (const int4*)g_w2lo[h];
            int4* d1 = (int4*)(smem + SM_WHI);
            int4* d2 = (int4*)(smem + SM_WLO);
            for (int i = t; i < 2048; i += 256) { d1[i] = s1[i]; d2[i] = s2[i]; }
        }
        __syncthreads();

        // ---- phase 2 partial: H chunk @ W2chunk -> e ----
#pragma unroll 1
        for (int ks = 0; ks < 8; ks++) {
            uint32_t ahi[2][4], alo[2][4];
#pragma unroll
            for (int mt = 0; mt < 2; mt++) {
                int row = m0 + mt * 16 + (lane & 15);
                int ch  = ks * 2 + (lane >> 4);
                ldm_x4(ahi[mt], img_addr(sb + SM_HHI, row, ch));
                ldm_x4(alo[mt], img_addr(sb + SM_HLO, row, ch));
            }
            int brow_lo = lane & 7;
            int bch     = ks * 2 + ((lane >> 3) & 1);
#pragma unroll
            for (int nt = 0; nt < 8; nt++) {
                uint32_t bhi[2], blo[2];
                int row = n0 + nt * 8 + brow_lo;
                ldm_x2(bhi, img_addr(sb + SM_WHI, row, bch));
                ldm_x2(blo, img_addr(sb + SM_WLO, row, bch));
#pragma unroll
                for (int mt = 0; mt < 2; mt++) {
                    mma_bf16(e[mt][nt], ahi[mt], bhi);
                    mma_bf16(e[mt][nt], ahi[mt], blo);
                    mma_bf16(e[mt][nt], alo[mt], bhi);
                }
            }
        }
    }

    // ---- final epilogue: bias + gelu + mean over 16 edges ----
#pragma unroll
    for (int mt = 0; mt < 2; mt++) {
        int pl = wm * 2 + mt;                  // local point 0..7
#pragma unroll
        for (int nt = 0; nt < 8; nt++) {
            int colb = n0 + nt * 8 + (lane & 3) * 2;
            float bv0 = b2s[colb], bv1 = b2s[colb + 1];
            float s0 = gelu_exact(e[mt][nt][0] + bv0) + gelu_exact(e[mt][nt][2] + bv0);
            float s1 = gelu_exact(e[mt][nt][1] + bv1) + gelu_exact(e[mt][nt][3] + bv1);
            s0 += __shfl_down_sync(0xffffffffu, s0, 16);
            s0 += __shfl_down_sync(0xffffffffu, s0, 8);
            s0 += __shfl_down_sync(0xffffffffu, s0, 4);
            s1 += __shfl_down_sync(0xffffffffu, s1, 16);
            s1 += __shfl_down_sync(0xffffffffu, s1, 8);
            s1 += __shfl_down_sync(0xffffffffu, s1, 4);
            if (lane < 4) {
                float* op = out + ((size_t)b * N_ + nbase + pl) * P_ + colb;
                op[0] = s0 * (1.0f / 16.0f);
                op[1] = s1 * (1.0f / 16.0f);
            }
        }
    }
}

// ---------------------------------------------------------------------------
extern "C" void kernel_launch(void* const* d_in, const int* in_sizes, int n_in,
                              void* d_out, int out_size)
{
    const float* points   = (const float*)d_in[0];
    const float* features = (const float*)d_in[1];
    const float* W1       = (const float*)d_in[2];
    const float* b1       = (const float*)d_in[3];
    const float* W2       = (const float*)d_in[4];
    const float* b2       = (const float*)d_in[5];
    float* out = (float*)d_out;

    cudaFuncSetAttribute(mlp_kernel, cudaFuncAttributeMaxDynamicSharedMemorySize,
                         SMEM_TOTAL);

    prep_kernel<<<256, 256>>>(W1, W2);
    knn_kernel<<<B_ * 4, 256>>>(points);
    mlp_kernel<<<(B_ * N_) / NPB, 256, SMEM_TOTAL>>>(features, b1, b2, out);
}

// round 11
// speedup vs baseline: 1.5914x; 1.1133x over previous
#include <cuda_runtime.h>
#include <cuda_bf16.h>
#include <math_constants.h>
#include <cstdint>

#define B_   32
#define N_   1024
#define F_   64
#define K_   16
#define P_   128
#define H_   256
#define NPB  8              // points per block
#define M_   128            // GEMM rows per block
#define THR  512            // threads per block (16 warps)

typedef unsigned long long ull;

// ---------------------------------------------------------------------------
// device scratch (static — no allocation)
// g_w1: half h (output cols h*128..): image [128 n_local][128 k] bf16
// g_w2: chunk c (k cols c*128..):     image [128 p][128 j_local] bf16
// ---------------------------------------------------------------------------
__device__ int g_idx[B_ * N_ * K_];
__device__ __align__(16) unsigned char g_w1hi[2][32768];
__device__ __align__(16) unsigned char g_w1lo[2][32768];
__device__ __align__(16) unsigned char g_w2hi[2][32768];
__device__ __align__(16) unsigned char g_w2lo[2][32768];

// ---------------------------------------------------------------------------
// SMEM layout (dynamic, bytes)
// ---------------------------------------------------------------------------
#define SM_AHI  0
#define SM_ALO  32768
#define SM_HHI  65536
#define SM_HLO  98304
#define SM_WHI  131072
#define SM_WLO  163840
#define SM_MISC 196608
#define SM_NBS  (SM_MISC + 0)        // 128 ints
#define SM_CENS (SM_MISC + 512)      // 512 floats
#define SM_B1S  (SM_MISC + 2560)     // 256 floats
#define SM_B2S  (SM_MISC + 3584)     // 128 floats
#define SMEM_TOTAL (SM_MISC + 4096)

// ---------------------------------------------------------------------------
// image addressing: row-major [R rows][128 bf16], 256B/row,
// 16B chunks XOR-swizzled by row&7 -> conflict-free ldmatrix
// ---------------------------------------------------------------------------
__device__ __forceinline__ uint32_t img_off(int r, int c)
{
    return (uint32_t)(r * 256) + (uint32_t)((((c >> 3) ^ (r & 7)) << 4) + (c & 7) * 2);
}
__device__ __forceinline__ uint32_t img_addr(uint32_t base, int row, int chunk)
{
    return base + (uint32_t)(row * 256) + (uint32_t)(((chunk ^ (row & 7)) << 4));
}

__device__ __forceinline__ uint32_t smem_to_u32(const void* p)
{
    uint32_t a;
    asm("{ .reg .u64 t; cvta.to.shared.u64 t, %1; cvt.u32.u64 %0, t; }"
        : "=r"(a) : "l"(p));
    return a;
}

// ---------------------------------------------------------------------------
// ldmatrix / mma wrappers (baseline PTX, no sm_103a-gated features)
// ---------------------------------------------------------------------------
__device__ __forceinline__ void ldm_x4(uint32_t* r, uint32_t addr)
{
    asm volatile("ldmatrix.sync.aligned.m8n8.x4.shared.b16 {%0,%1,%2,%3}, [%4];"
                 : "=r"(r[0]), "=r"(r[1]), "=r"(r[2]), "=r"(r[3]) : "r"(addr));
}
__device__ __forceinline__ void mma_bf16(float* d, const uint32_t* a, const uint32_t* b)
{
    asm volatile(
        "mma.sync.aligned.m16n8k16.row.col.f32.bf16.bf16.f32 "
        "{%0,%1,%2,%3}, {%4,%5,%6,%7}, {%8,%9}, {%0,%1,%2,%3};"
        : "+f"(d[0]), "+f"(d[1]), "+f"(d[2]), "+f"(d[3])
        : "r"(a[0]), "r"(a[1]), "r"(a[2]), "r"(a[3]), "r"(b[0]), "r"(b[1]));
}

__device__ __forceinline__ uint32_t pk2(__nv_bfloat16 a, __nv_bfloat16 b)
{
    uint16_t ua = *(uint16_t*)&a, ub = *(uint16_t*)&b;
    return (uint32_t)ua | ((uint32_t)ub << 16);
}
__device__ __forceinline__ void split4(float v0, float v1, float v2, float v3,
                                       ull& hi, ull& lo)
{
    __nv_bfloat16 h0 = __float2bfloat16(v0), h1 = __float2bfloat16(v1);
    __nv_bfloat16 h2 = __float2bfloat16(v2), h3 = __float2bfloat16(v3);
    __nv_bfloat16 l0 = __float2bfloat16(v0 - __bfloat162float(h0));
    __nv_bfloat16 l1 = __float2bfloat16(v1 - __bfloat162float(h1));
    __nv_bfloat16 l2 = __float2bfloat16(v2 - __bfloat162float(h2));
    __nv_bfloat16 l3 = __float2bfloat16(v3 - __bfloat162float(h3));
    hi = (ull)pk2(h0, h1) | ((ull)pk2(h2, h3) << 32);
    lo = (ull)pk2(l0, l1) | ((ull)pk2(l2, l3) << 32);
}
__device__ __forceinline__ void split2(float v0, float v1, uint32_t& hi, uint32_t& lo)
{
    __nv_bfloat16 h0 = __float2bfloat16(v0), h1 = __float2bfloat16(v1);
    __nv_bfloat16 l0 = __float2bfloat16(v0 - __bfloat162float(h0));
    __nv_bfloat16 l1 = __float2bfloat16(v1 - __bfloat162float(h1));
    hi = pk2(h0, h1); lo = pk2(l0, l1);
}
__device__ __forceinline__ float gelu_exact(float x)
{
    return 0.5f * x * (1.0f + erff(x * 0.70710678118654752440f));
}

// ---------------------------------------------------------------------------
// Kernel 0: weight prep — transpose + bf16 split into swizzled images
// ---------------------------------------------------------------------------
__global__ __launch_bounds__(256) void prep_kernel(const float* __restrict__ W1,
                                                   const float* __restrict__ W2)
{
    int i = blockIdx.x * 256 + threadIdx.x;
    if (i < 32768) {                       // W1^T: n 0..255, k 0..127
        int n = i >> 7, k = i & 127;
        float v = W1[k * H_ + n];
        __nv_bfloat16 h = __float2bfloat16(v);
        __nv_bfloat16 l = __float2bfloat16(v - __bfloat162float(h));
        int hh = n >> 7, nl = n & 127;
        uint32_t off = img_off(nl, k);
        *(__nv_bfloat16*)(g_w1hi[hh] + off) = h;
        *(__nv_bfloat16*)(g_w1lo[hh] + off) = l;
    } else {                               // W2^T: p 0..127, j 0..255
        int j2 = i - 32768;
        int p = j2 >> 8, j = j2 & 255;
        float v = W2[j * P_ + p];
        __nv_bfloat16 h = __float2bfloat16(v);
        __nv_bfloat16 l = __float2bfloat16(v - __bfloat162float(h));
        int c = j >> 7, jl = j & 127;
        uint32_t off = img_off(p, jl);
        *(__nv_bfloat16*)(g_w2hi[c] + off) = h;
        *(__nv_bfloat16*)(g_w2lo[c] + off) = l;
    }
}

// ---------------------------------------------------------------------------
// Kernel 1: KNN (proven correct, unchanged)
// ---------------------------------------------------------------------------
__global__ __launch_bounds__(256) void knn_kernel(const float* __restrict__ points)
{
    __shared__ float4 pts[N_];
    int b = blockIdx.x >> 2;
    int rowbase = (blockIdx.x & 3) << 8;
    const float* P = points + (size_t)b * N_ * 3;
    for (int i = threadIdx.x; i < N_; i += 256) {
        float x = P[i * 3 + 0], y = P[i * 3 + 1], z = P[i * 3 + 2];
        pts[i] = make_float4(x, y, z, x * x + y * y + z * z);
    }
    __syncthreads();

    int n = rowbase + threadIdx.x;
    float4 pn = pts[n];

    float dist[K_ + 1];
    int   nbr[K_ + 1];
#pragma unroll
    for (int j = 0; j <= K_; j++) { dist[j] = CUDART_INF_F; nbr[j] = 0; }
    float worst = CUDART_INF_F;

    for (int m = 0; m < N_; m++) {
        float4 pm = pts[m];
        float dot = pn.x * pm.x + pn.y * pm.y + pn.z * pm.z;
        float d = pn.w - 2.0f * dot + pm.w + 1e-5f;
        if (d < worst) {
            int j = K_;
            for (; j > 0; j--) {
                if (dist[j - 1] > d) { dist[j] = dist[j - 1]; nbr[j] = nbr[j - 1]; }
                else break;
            }
            dist[j] = d; nbr[j] = m;
            worst = dist[K_];
        }
    }

    int* o = g_idx + ((size_t)b * N_ + n) * K_;
#pragma unroll
    for (int k = 0; k < K_; k++) o[k] = nbr[k + 1];
}

// ---------------------------------------------------------------------------
// Kernel 2: fused edge-MLP via split-bf16 mma.sync (3 products, fp32 acc).
// Block = 8 points = 128 edge rows, 16 warps (4 M-groups x 4 N-groups),
// warp tile 32x32. For h in {0,1}:
//   phase1 half: D1[:,h*128..] = A[128x128] @ W1half  -> bias+gelu -> H chunk
//   phase2 part: D2 += H chunk @ W2chunk(h)           (acc in registers)
// Final: bias+gelu+mean16 -> out.
// ---------------------------------------------------------------------------
__global__ __launch_bounds__(THR, 1) void mlp_kernel(
    const float* __restrict__ features,
    const float* __restrict__ b1, const float* __restrict__ b2,
    float* __restrict__ out)
{
    extern __shared__ __align__(1024) char smem[];
    uint32_t sb = smem_to_u32(smem);
    int t = threadIdx.x, wid = t >> 5, lane = t & 31;

    int blk = blockIdx.x;
    int b     = blk >> 7;
    int nbase = (blk & 127) * NPB;
    const float* Fb = features + (size_t)b * N_ * F_;

    int*   nbS  = (int*)(smem + SM_NBS);
    float* cenS = (float*)(smem + SM_CENS);
    float* b1s  = (float*)(smem + SM_B1S);
    float* b2s  = (float*)(smem + SM_B2S);

    for (int i = t; i < NPB * F_; i += THR)
        cenS[i] = Fb[(size_t)(nbase + (i >> 6)) * F_ + (i & 63)];
    if (t < M_) nbS[t] = g_idx[((size_t)b * N_ + nbase + (t >> 4)) * K_ + (t & 15)];
    if (t < H_) b1s[t] = b1[t];
    if (t >= H_ && t < H_ + P_) b2s[t - H_] = b2[t - H_];
    __syncthreads();

    // ---- build A image (hi/lo bf16, swizzled) ----
    for (int i = t; i < 4096; i += THR) {
        int m  = i >> 5;
        int fg = (i & 31) << 2;
        float v0, v1, v2, v3;
        if (fg < 64) {
            float4 nv = *(const float4*)(Fb + (size_t)nbS[m] * F_ + fg);
            float4 cv = *(const float4*)(cenS + (m >> 4) * F_ + fg);
            v0 = nv.x - cv.x; v1 = nv.y - cv.y; v2 = nv.z - cv.z; v3 = nv.w - cv.w;
        } else {
            float4 cv = *(const float4*)(cenS + (m >> 4) * F_ + (fg - 64));
            v0 = cv.x; v1 = cv.y; v2 = cv.z; v3 = cv.w;
        }
        ull hi, lo; split4(v0, v1, v2, v3, hi, lo);
        uint32_t off = img_off(m, fg);
        *(ull*)(smem + SM_AHI + off) = hi;
        *(ull*)(smem + SM_ALO + off) = lo;
    }

    int wm = wid & 3, wg = wid >> 2;      // 4 M-groups x 4 N-groups
    int m0 = wm * 32;
    int n0 = wg * 32;

    float e[2][4][4];
#pragma unroll
    for (int mt = 0; mt < 2; mt++)
#pragma unroll
        for (int nt = 0; nt < 4; nt++)
#pragma unroll
            for (int r = 0; r < 4; r++) e[mt][nt][r] = 0.0f;

#pragma unroll 1
    for (int h = 0; h < 2; h++) {
        // ---- load W1 half images (W region) ----
        __syncthreads();
        {
            const int4* s1 = (const int4*)g_w1hi[h];
            const int4* s2 = (const int4*)g_w1lo[h];
            int4* d1 = (int4*)(smem + SM_WHI);
            int4* d2 = (int4*)(smem + SM_WLO);
            for (int i = t; i < 2048; i += THR) { d1[i] = s1[i]; d2[i] = s2[i]; }
        }
        __syncthreads();

        // ---- phase 1: A[128x128] @ W1half -> d ----
        float d[2][4][4];
#pragma unroll
        for (int mt = 0; mt < 2; mt++)
#pragma unroll
            for (int nt = 0; nt < 4; nt++)
#pragma unroll
                for (int r = 0; r < 4; r++) d[mt][nt][r] = 0.0f;

#pragma unroll 1
        for (int ks = 0; ks < 8; ks++) {
            uint32_t ahi[2][4], alo[2][4];
#pragma unroll
            for (int mt = 0; mt < 2; mt++) {
                int row = m0 + mt * 16 + (lane & 15);
                int ch  = ks * 2 + (lane >> 4);
                ldm_x4(ahi[mt], img_addr(sb + SM_AHI, row, ch));
                ldm_x4(alo[mt], img_addr(sb + SM_ALO, row, ch));
            }
            // B fragments: one x4 covers 2 n-tiles x 2 k-chunks
            int brow = (lane & 7) + ((lane >> 4) << 3);
            int bch  = ks * 2 + ((lane >> 3) & 1);
#pragma unroll
            for (int ntp = 0; ntp < 2; ntp++) {
                uint32_t bhi[4], blo[4];
                int row = n0 + ntp * 16 + brow;
                ldm_x4(bhi, img_addr(sb + SM_WHI, row, bch));
                ldm_x4(blo, img_addr(sb + SM_WLO, row, bch));
#pragma unroll
                for (int half = 0; half < 2; half++) {
                    int nt = ntp * 2 + half;
#pragma unroll
                    for (int mt = 0; mt < 2; mt++) {
                        mma_bf16(d[mt][nt], ahi[mt], bhi + 2 * half);
                        mma_bf16(d[mt][nt], ahi[mt], blo + 2 * half);
                        mma_bf16(d[mt][nt], alo[mt], bhi + 2 * half);
                    }
                }
            }
        }

        // ---- epilogue: bias + gelu -> H images ----
#pragma unroll
        for (int mt = 0; mt < 2; mt++) {
            int row0 = m0 + mt * 16 + (lane >> 2);
#pragma unroll
            for (int nt = 0; nt < 4; nt++) {
                int colb = n0 + nt * 8 + (lane & 3) * 2;
                float bv0 = b1s[h * 128 + colb], bv1 = b1s[h * 128 + colb + 1];
                float v0 = gelu_exact(d[mt][nt][0] + bv0);
                float v1 = gelu_exact(d[mt][nt][1] + bv1);
                float v2 = gelu_exact(d[mt][nt][2] + bv0);
                float v3 = gelu_exact(d[mt][nt][3] + bv1);
                uint32_t hi, lo;
                split2(v0, v1, hi, lo);
                uint32_t off = img_off(row0, colb);
                *(uint32_t*)(smem + SM_HHI + off) = hi;
                *(uint32_t*)(smem + SM_HLO + off) = lo;
                split2(v2, v3, hi, lo);
                off = img_off(row0 + 8, colb);
                *(uint32_t*)(smem + SM_HHI + off) = hi;
                *(uint32_t*)(smem + SM_HLO + off) = lo;
            }
        }
        __syncthreads();

        // ---- load W2 chunk images (overwrite W region) ----
        {
            const int4* s1 = (const int4*)g_w2hi[h];
            const int4* s2 = (const int4*)g_w2lo[h];
            int4* d1 = (int4*)(smem + SM_WHI);
            int4* d2 = (int4*)(smem + SM_WLO);
            for (int i = t; i < 2048; i += THR) { d1[i] = s1[i]; d2[i] = s2[i]; }
        }
        __syncthreads();

        // ---- phase 2 partial: H chunk @ W2chunk -> e ----
#pragma unroll 1
        for (int ks = 0; ks < 8; ks++) {
            uint32_t ahi[2][4], alo[2][4];
#pragma unroll
            for (int mt = 0; mt < 2; mt++) {
                int row = m0 + mt * 16 + (lane & 15);
                int ch  = ks * 2 + (lane >> 4);
                ldm_x4(ahi[mt], img_addr(sb + SM_HHI, row, ch));
                ldm_x4(alo[mt], img_addr(sb + SM_HLO, row, ch));
            }
            int brow = (lane & 7) + ((lane >> 4) << 3);
            int bch  = ks * 2 + ((lane >> 3) & 1);
#pragma unroll
            for (int ntp = 0; ntp < 2; ntp++) {
                uint32_t bhi[4], blo[4];
                int row = n0 + ntp * 16 + brow;
                ldm_x4(bhi, img_addr(sb + SM_WHI, row, bch));
                ldm_x4(blo, img_addr(sb + SM_WLO, row, bch));
#pragma unroll
                for (int half = 0; half < 2; half++) {
                    int nt = ntp * 2 + half;
#pragma unroll
                    for (int mt = 0; mt < 2; mt++) {
                        mma_bf16(e[mt][nt], ahi[mt], bhi + 2 * half);
                        mma_bf16(e[mt][nt], ahi[mt], blo + 2 * half);
                        mma_bf16(e[mt][nt], alo[mt], bhi + 2 * half);
                    }
                }
            }
        }
    }

    // ---- final epilogue: bias + gelu + mean over 16 edges ----
#pragma unroll
    for (int mt = 0; mt < 2; mt++) {
        int pl = wm * 2 + mt;                  // local point 0..7
#pragma unroll
        for (int nt = 0; nt < 4; nt++) {
            int colb = n0 + nt * 8 + (lane & 3) * 2;
            float bv0 = b2s[colb], bv1 = b2s[colb + 1];
            float s0 = gelu_exact(e[mt][nt][0] + bv0) + gelu_exact(e[mt][nt][2] + bv0);
            float s1 = gelu_exact(e[mt][nt][1] + bv1) + gelu_exact(e[mt][nt][3] + bv1);
            s0 += __shfl_down_sync(0xffffffffu, s0, 16);
            s0 += __shfl_down_sync(0xffffffffu, s0, 8);
            s0 += __shfl_down_sync(0xffffffffu, s0, 4);
            s1 += __shfl_down_sync(0xffffffffu, s1, 16);
            s1 += __shfl_down_sync(0xffffffffu, s1, 8);
            s1 += __shfl_down_sync(0xffffffffu, s1, 4);
            if (lane < 4) {
                float* op = out + ((size_t)b * N_ + nbase + pl) * P_ + colb;
                op[0] = s0 * (1.0f / 16.0f);
                op[1] = s1 * (1.0f / 16.0f);
            }
        }
    }
}

// ---------------------------------------------------------------------------
extern "C" void kernel_launch(void* const* d_in, const int* in_sizes, int n_in,
                              void* d_out, int out_size)
{
    const float* points   = (const float*)d_in[0];
    const float* features = (const float*)d_in[1];
    const float* W1       = (const float*)d_in[2];
    const float* b1       = (const float*)d_in[3];
    const float* W2       = (const float*)d_in[4];
    const float* b2       = (const float*)d_in[5];
    float* out = (float*)d_out;

    cudaFuncSetAttribute(mlp_kernel, cudaFuncAttributeMaxDynamicSharedMemorySize,
                         SMEM_TOTAL);

    prep_kernel<<<256, 256>>>(W1, W2);
    knn_kernel<<<B_ * 4, 256>>>(points);
    mlp_kernel<<<(B_ * N_) / NPB, THR, SMEM_TOTAL>>>(features, b1, b2, out);
}

// round 14
// speedup vs baseline: 1.8286x; 1.1490x over previous
#include <cuda_runtime.h>
#include <cuda_bf16.h>
#include <math_constants.h>
#include <cstdint>

#define B_   32
#define N_   1024
#define F_   64
#define K_   16
#define P_   128
#define H_   256
#define NPB  4              // points per block
#define M_   64             // GEMM rows per block
#define THR  256            // 8 warps

typedef unsigned long long ull;

// ---------------------------------------------------------------------------
// device scratch (static — no allocation)
// Fragment tables: 16B per (ks, ntile, lane) = {bhi0, bhi1, blo0, blo1}
// g_w1f[h][ks][nt][lane], h: output half, nt: 16 tiles of 8 cols in the half
// g_w2f[c][ks][nt][lane], c: k-chunk of 128, nt: 16 tiles of 8 output cols
// ---------------------------------------------------------------------------
__device__ int g_idx[B_ * N_ * K_];
__device__ __align__(16) uint4 g_w1f[2 * 8 * 16 * 32];   // 64 KB
__device__ __align__(16) uint4 g_w2f[2 * 8 * 16 * 32];   // 64 KB

// ---------------------------------------------------------------------------
// SMEM layout (dynamic, bytes)
// ---------------------------------------------------------------------------
#define SM_AHI  0            // 16384 (A image hi: 64 rows x 256B)
#define SM_ALO  16384        // 16384
#define SM_HHI  32768        // 16384 (H image for current half)
#define SM_HLO  49152        // 16384
#define SM_MISC 65536
#define SM_NBS  (SM_MISC + 0)        // 64 ints
#define SM_CENS (SM_MISC + 256)      // 256 floats
#define SM_B1S  (SM_MISC + 1280)     // 256 floats
#define SM_B2S  (SM_MISC + 2304)     // 128 floats
#define SMEM_TOTAL (SM_MISC + 2816)

// ---------------------------------------------------------------------------
// image addressing: row-major [rows][128 bf16], 256B/row,
// 16B chunks XOR-swizzled by row&7 -> conflict-free ldmatrix
// ---------------------------------------------------------------------------
__device__ __forceinline__ uint32_t img_off(int r, int c)
{
    return (uint32_t)(r * 256) + (uint32_t)((((c >> 3) ^ (r & 7)) << 4) + (c & 7) * 2);
}
__device__ __forceinline__ uint32_t img_addr(uint32_t base, int row, int chunk)
{
    return base + (uint32_t)(row * 256) + (uint32_t)(((chunk ^ (row & 7)) << 4));
}

__device__ __forceinline__ uint32_t smem_to_u32(const void* p)
{
    uint32_t a;
    asm("{ .reg .u64 t; cvta.to.shared.u64 t, %1; cvt.u32.u64 %0, t; }"
        : "=r"(a) : "l"(p));
    return a;
}

// ---------------------------------------------------------------------------
// ldmatrix / mma wrappers (baseline PTX, no sm_103a-gated features)
// ---------------------------------------------------------------------------
__device__ __forceinline__ void ldm_x4(uint32_t* r, uint32_t addr)
{
    asm volatile("ldmatrix.sync.aligned.m8n8.x4.shared.b16 {%0,%1,%2,%3}, [%4];"
                 : "=r"(r[0]), "=r"(r[1]), "=r"(r[2]), "=r"(r[3]) : "r"(addr));
}
__device__ __forceinline__ void mma_bf16(float* d, const uint32_t* a, const uint32_t* b)
{
    asm volatile(
        "mma.sync.aligned.m16n8k16.row.col.f32.bf16.bf16.f32 "
        "{%0,%1,%2,%3}, {%4,%5,%6,%7}, {%8,%9}, {%0,%1,%2,%3};"
        : "+f"(d[0]), "+f"(d[1]), "+f"(d[2]), "+f"(d[3])
        : "r"(a[0]), "r"(a[1]), "r"(a[2]), "r"(a[3]), "r"(b[0]), "r"(b[1]));
}

__device__ __forceinline__ uint32_t pk2(__nv_bfloat16 a, __nv_bfloat16 b)
{
    uint16_t ua = *(uint16_t*)&a, ub = *(uint16_t*)&b;
    return (uint32_t)ua | ((uint32_t)ub << 16);
}
__device__ __forceinline__ void split4(float v0, float v1, float v2, float v3,
                                       ull& hi, ull& lo)
{
    __nv_bfloat16 h0 = __float2bfloat16(v0), h1 = __float2bfloat16(v1);
    __nv_bfloat16 h2 = __float2bfloat16(v2), h3 = __float2bfloat16(v3);
    __nv_bfloat16 l0 = __float2bfloat16(v0 - __bfloat162float(h0));
    __nv_bfloat16 l1 = __float2bfloat16(v1 - __bfloat162float(h1));
    __nv_bfloat16 l2 = __float2bfloat16(v2 - __bfloat162float(h2));
    __nv_bfloat16 l3 = __float2bfloat16(v3 - __bfloat162float(h3));
    hi = (ull)pk2(h0, h1) | ((ull)pk2(h2, h3) << 32);
    lo = (ull)pk2(l0, l1) | ((ull)pk2(l2, l3) << 32);
}
__device__ __forceinline__ void split2(float v0, float v1, uint32_t& hi, uint32_t& lo)
{
    __nv_bfloat16 h0 = __float2bfloat16(v0), h1 = __float2bfloat16(v1);
    __nv_bfloat16 l0 = __float2bfloat16(v0 - __bfloat162float(h0));
    __nv_bfloat16 l1 = __float2bfloat16(v1 - __bfloat162float(h1));
    hi = pk2(h0, h1); lo = pk2(l0, l1);
}
__device__ __forceinline__ float gelu_exact(float x)
{
    return 0.5f * x * (1.0f + erff(x * 0.70710678118654752440f));
}

// ---------------------------------------------------------------------------
// Kernel 0: weight prep — build B-fragment tables (split bf16 hi/lo).
// Thread i -> one (matrix, h/c, ks, nt, lane) 16B entry.
// Fragment spec m16n8k16 'col' B: n' = lane>>2, k0 = 2*(lane&3); b1: k0+8.
// ---------------------------------------------------------------------------
__global__ __launch_bounds__(256) void prep_kernel(const float* __restrict__ W1,
                                                   const float* __restrict__ W2)
{
    int i = blockIdx.x * 256 + threadIdx.x;      // 0 .. 16383
    int mat  = i >> 13;
    int rem  = i & 8191;
    int h    = rem >> 12;
    int ks   = (rem >> 9) & 7;
    int nt   = (rem >> 5) & 15;
    int lane = rem & 31;

    int np = nt * 8 + (lane >> 2);               // n (W1) / p (W2) index in tile group
    int k0 = ks * 16 + (lane & 3) * 2;

    float v[4];
    if (mat == 0) {                              // W1: n' = h*128+np, k = k0..
        int n = h * 128 + np;
        v[0] = W1[(k0 + 0) * H_ + n];
        v[1] = W1[(k0 + 1) * H_ + n];
        v[2] = W1[(k0 + 8) * H_ + n];
        v[3] = W1[(k0 + 9) * H_ + n];
    } else {                                     // W2: p = np, j = h*128 + k0..
        int j = h * 128 + k0;
        v[0] = W2[(j + 0) * P_ + np];
        v[1] = W2[(j + 1) * P_ + np];
        v[2] = W2[(j + 8) * P_ + np];
        v[3] = W2[(j + 9) * P_ + np];
    }
    __nv_bfloat16 hi0 = __float2bfloat16(v[0]), hi1 = __float2bfloat16(v[1]);
    __nv_bfloat16 hi2 = __float2bfloat16(v[2]), hi3 = __float2bfloat16(v[3]);
    __nv_bfloat16 lo0 = __float2bfloat16(v[0] - __bfloat162float(hi0));
    __nv_bfloat16 lo1 = __float2bfloat16(v[1] - __bfloat162float(hi1));
    __nv_bfloat16 lo2 = __float2bfloat16(v[2] - __bfloat162float(hi2));
    __nv_bfloat16 lo3 = __float2bfloat16(v[3] - __bfloat162float(hi3));

    uint4 frag;
    frag.x = pk2(hi0, hi1);     // bhi0
    frag.y = pk2(hi2, hi3);     // bhi1
    frag.z = pk2(lo0, lo1);     // blo0
    frag.w = pk2(lo2, lo3);     // blo1

    int idx = (((h * 8 + ks) * 16) + nt) * 32 + lane;
    if (mat == 0) g_w1f[idx] = frag;
    else          g_w2f[idx] = frag;
}

// ---------------------------------------------------------------------------
// Kernel 1: KNN (proven correct, unchanged)
// ---------------------------------------------------------------------------
__global__ __launch_bounds__(256) void knn_kernel(const float* __restrict__ points)
{
    __shared__ float4 pts[N_];
    int b = blockIdx.x >> 2;
    int rowbase = (blockIdx.x & 3) << 8;
    const float* P = points + (size_t)b * N_ * 3;
    for (int i = threadIdx.x; i < N_; i += 256) {
        float x = P[i * 3 + 0], y = P[i * 3 + 1], z = P[i * 3 + 2];
        pts[i] = make_float4(x, y, z, x * x + y * y + z * z);
    }
    __syncthreads();

    int n = rowbase + threadIdx.x;
    float4 pn = pts[n];

    float dist[K_ + 1];
    int   nbr[K_ + 1];
#pragma unroll
    for (int j = 0; j <= K_; j++) { dist[j] = CUDART_INF_F; nbr[j] = 0; }
    float worst = CUDART_INF_F;

    for (int m = 0; m < N_; m++) {
        float4 pm = pts[m];
        float dot = pn.x * pm.x + pn.y * pm.y + pn.z * pm.z;
        float d = pn.w - 2.0f * dot + pm.w + 1e-5f;
        if (d < worst) {
            int j = K_;
            for (; j > 0; j--) {
                if (dist[j - 1] > d) { dist[j] = dist[j - 1]; nbr[j] = nbr[j - 1]; }
                else break;
            }
            dist[j] = d; nbr[j] = m;
            worst = dist[K_];
        }
    }

    int* o = g_idx + ((size_t)b * N_ + n) * K_;
#pragma unroll
    for (int k = 0; k < K_; k++) o[k] = nbr[k + 1];
}

// ---------------------------------------------------------------------------
// Kernel 2: fused edge-MLP via split-bf16 mma.sync (3 products, fp32 acc).
// Block = 4 points = 64 edge rows, 8 warps (2 M-groups x 4 N-groups),
// warp tile 32x32. Weights come straight from L1/L2 as prepacked fragments
// (one LDG.128 per n-tile per ks) — no weight staging in SMEM.
// For h in {0,1}:
//   phase1 half: D1[:,h*128..] = A[64x128] @ W1half -> bias+gelu -> H image
//   phase2 part: D2 += H @ W2chunk(h)               (acc in registers)
// Final: bias+gelu+mean16 -> out.
// ---------------------------------------------------------------------------
__global__ __launch_bounds__(THR, 2) void mlp_kernel(
    const float* __restrict__ features,
    const float* __restrict__ b1, const float* __restrict__ b2,
    float* __restrict__ out)
{
    extern __shared__ __align__(1024) char smem[];
    uint32_t sb = smem_to_u32(smem);
    int t = threadIdx.x, wid = t >> 5, lane = t & 31;

    int blk   = blockIdx.x;
    int b     = blk >> 8;
    int nbase = (blk & 255) * NPB;
    const float* Fb = features + (size_t)b * N_ * F_;

    int*   nbS  = (int*)(smem + SM_NBS);
    float* cenS = (float*)(smem + SM_CENS);
    float* b1s  = (float*)(smem + SM_B1S);
    float* b2s  = (float*)(smem + SM_B2S);

    for (int i = t; i < NPB * F_; i += THR)
        cenS[i] = Fb[(size_t)(nbase + (i >> 6)) * F_ + (i & 63)];
    if (t < M_) nbS[t] = g_idx[((size_t)b * N_ + nbase + (t >> 4)) * K_ + (t & 15)];
    b1s[t] = b1[t];
    if (t < P_) b2s[t] = b2[t];
    __syncthreads();

    // ---- build A image (hi/lo bf16, swizzled): 64 rows x 128 cols ----
    for (int i = t; i < 2048; i += THR) {
        int m  = i >> 5;
        int fg = (i & 31) << 2;
        float v0, v1, v2, v3;
        if (fg < 64) {
            float4 nv = *(const float4*)(Fb + (size_t)nbS[m] * F_ + fg);
            float4 cv = *(const float4*)(cenS + (m >> 4) * F_ + fg);
            v0 = nv.x - cv.x; v1 = nv.y - cv.y; v2 = nv.z - cv.z; v3 = nv.w - cv.w;
        } else {
            float4 cv = *(const float4*)(cenS + (m >> 4) * F_ + (fg - 64));
            v0 = cv.x; v1 = cv.y; v2 = cv.z; v3 = cv.w;
        }
        ull hi, lo; split4(v0, v1, v2, v3, hi, lo);
        uint32_t off = img_off(m, fg);
        *(ull*)(smem + SM_AHI + off) = hi;
        *(ull*)(smem + SM_ALO + off) = lo;
    }

    int wm = wid & 1, wg = wid >> 1;      // 2 M-groups x 4 N-groups
    int m0 = wm * 32;
    int n0 = wg * 32;                     // within 128-col half / output

    float e[2][4][4];
#pragma unroll
    for (int mt = 0; mt < 2; mt++)
#pragma unroll
        for (int nt = 0; nt < 4; nt++)
#pragma unroll
            for (int r = 0; r < 4; r++) e[mt][nt][r] = 0.0f;

#pragma unroll 1
    for (int h = 0; h < 2; h++) {
        // h=0: A image just built (sync above covers it).
        // h=1: must not overwrite H until phase2(h=0) finished reading it.
        __syncthreads();

        // ---- phase 1: A[64x128] @ W1half -> d ----
        float d[2][4][4];
#pragma unroll
        for (int mt = 0; mt < 2; mt++)
#pragma unroll
            for (int nt = 0; nt < 4; nt++)
#pragma unroll
                for (int r = 0; r < 4; r++) d[mt][nt][r] = 0.0f;

#pragma unroll 1
        for (int ks = 0; ks < 8; ks++) {
            uint32_t ahi[2][4], alo[2][4];
#pragma unroll
            for (int mt = 0; mt < 2; mt++) {
                int row = m0 + mt * 16 + (lane & 15);
                int ch  = ks * 2 + (lane >> 4);
                ldm_x4(ahi[mt], img_addr(sb + SM_AHI, row, ch));
                ldm_x4(alo[mt], img_addr(sb + SM_ALO, row, ch));
            }
            const uint4* wf = g_w1f + (((h * 8 + ks) * 16) + wg * 4) * 32 + lane;
#pragma unroll
            for (int nt = 0; nt < 4; nt++) {
                uint4 frag = wf[nt * 32];
                uint32_t bhi[2] = {frag.x, frag.y};
                uint32_t blo[2] = {frag.z, frag.w};
#pragma unroll
                for (int mt = 0; mt < 2; mt++) {
                    mma_bf16(d[mt][nt], ahi[mt], bhi);
                    mma_bf16(d[mt][nt], ahi[mt], blo);
                    mma_bf16(d[mt][nt], alo[mt], bhi);
                }
            }
        }

        // ---- epilogue: bias + gelu -> H image (hi/lo) ----
#pragma unroll
        for (int mt = 0; mt < 2; mt++) {
            int row0 = m0 + mt * 16 + (lane >> 2);
#pragma unroll
            for (int nt = 0; nt < 4; nt++) {
                int colb = n0 + nt * 8 + (lane & 3) * 2;
                float bv0 = b1s[h * 128 + colb], bv1 = b1s[h * 128 + colb + 1];
                float v0 = gelu_exact(d[mt][nt][0] + bv0);
                float v1 = gelu_exact(d[mt][nt][1] + bv1);
                float v2 = gelu_exact(d[mt][nt][2] + bv0);
                float v3 = gelu_exact(d[mt][nt][3] + bv1);
                uint32_t hi, lo;
                split2(v0, v1, hi, lo);
                uint32_t off = img_off(row0, colb);
                *(uint32_t*)(smem + SM_HHI + off) = hi;
                *(uint32_t*)(smem + SM_HLO + off) = lo;
                split2(v2, v3, hi, lo);
                off = img_off(row0 + 8, colb);
                *(uint32_t*)(smem + SM_HHI + off) = hi;
                *(uint32_t*)(smem + SM_HLO + off) = lo;
            }
        }
        __syncthreads();

        // ---- phase 2 partial: H[64x128] @ W2chunk(h) -> e ----
#pragma unroll 1
        for (int ks = 0; ks < 8; ks++) {
            uint32_t ahi[2][4], alo[2][4];
#pragma unroll
            for (int mt = 0; mt < 2; mt++) {
                int row = m0 + mt * 16 + (lane & 15);
                int ch  = ks * 2 + (lane >> 4);
                ldm_x4(ahi[mt], img_addr(sb + SM_HHI, row, ch));
                ldm_x4(alo[mt], img_addr(sb + SM_HLO, row, ch));
            }
            const uint4* wf = g_w2f + (((h * 8 + ks) * 16) + wg * 4) * 32 + lane;
#pragma unroll
            for (int nt = 0; nt < 4; nt++) {
                uint4 frag = wf[nt * 32];
                uint32_t bhi[2] = {frag.x, frag.y};
                uint32_t blo[2] = {frag.z, frag.w};
#pragma unroll
                for (int mt = 0; mt < 2; mt++) {
                    mma_bf16(e[mt][nt], ahi[mt], bhi);
                    mma_bf16(e[mt][nt], ahi[mt], blo);
                    mma_bf16(e[mt][nt], alo[mt], bhi);
                }
            }
        }
    }

    // ---- final epilogue: bias + gelu + mean over 16 edges ----
#pragma unroll
    for (int mt = 0; mt < 2; mt++) {
        int pl = wm * 2 + mt;                  // local point 0..3
#pragma unroll
        for (int nt = 0; nt < 4; nt++) {
            int colb = n0 + nt * 8 + (lane & 3) * 2;
            float bv0 = b2s[colb], bv1 = b2s[colb + 1];
            float s0 = gelu_exact(e[mt][nt][0] + bv0) + gelu_exact(e[mt][nt][2] + bv0);
            float s1 = gelu_exact(e[mt][nt][1] + bv1) + gelu_exact(e[mt][nt][3] + bv1);
            s0 += __shfl_down_sync(0xffffffffu, s0, 16);
            s0 += __shfl_down_sync(0xffffffffu, s0, 8);
            s0 += __shfl_down_sync(0xffffffffu, s0, 4);
            s1 += __shfl_down_sync(0xffffffffu, s1, 16);
            s1 += __shfl_down_sync(0xffffffffu, s1, 8);
            s1 += __shfl_down_sync(0xffffffffu, s1, 4);
            if (lane < 4) {
                float* op = out + ((size_t)b * N_ + nbase + pl) * P_ + colb;
                op[0] = s0 * (1.0f / 16.0f);
                op[1] = s1 * (1.0f / 16.0f);
            }
        }
    }
}

// ---------------------------------------------------------------------------
extern "C" void kernel_launch(void* const* d_in, const int* in_sizes, int n_in,
                              void* d_out, int out_size)
{
    const float* points   = (const float*)d_in[0];
    const float* features = (const float*)d_in[1];
    const float* W1       = (const float*)d_in[2];
    const float* b1       = (const float*)d_in[3];
    const float* W2       = (const float*)d_in[4];
    const float* b2       = (const float*)d_in[5];
    float* out = (float*)d_out;

    cudaFuncSetAttribute(mlp_kernel, cudaFuncAttributeMaxDynamicSharedMemorySize,
                         SMEM_TOTAL);

    prep_kernel<<<64, 256>>>(W1, W2);
    knn_kernel<<<B_ * 4, 256>>>(points);
    mlp_kernel<<<(B_ * N_) / NPB, THR, SMEM_TOTAL>>>(features, b1, b2, out);
}